// round 4
// baseline (speedup 1.0000x reference)
#include <cuda_runtime.h>
#include <cstdint>

#define NB 8192           // batch
#define A1W 286           // 11*26 conv1 output pixels per batch elem

// ---------------- scratch (device globals; no allocation allowed) ----------
__device__ uint32_t g_lut1[512];                       // conv1+bn1+relu+binarize LUT
__device__ uint32_t g_wpos2[64 * 9];                   // conv2 weight sign bits [oc][tap]
__device__ float    g_c1_2[64], g_c0_2[64];            // conv2 bn affine
__device__ __align__(16) uint32_t g_wposL[512 * 128];  // lin weight bits [n(pad512)][j(pad128)]
__device__ uint32_t g_wposO[10 * 16];                  // out weight bits [k][g]
__device__ uint32_t g_A1[NB * A1W];                    // conv1 output, 32ch packed per pixel
__device__ uint32_t g_tT[120 * NB];                    // conv2 output bits, transposed [j][m]
__device__ __align__(16) uint32_t g_B2[NB * 16];       // lin output bits [m][16 words]

// ---------------- prep (misc): LUTs, conv2 weights, out weights ------------
__global__ void prep_misc_kernel(const float* __restrict__ conv1_w, const float* __restrict__ conv1_b,
                                 const float* __restrict__ bn1_g, const float* __restrict__ bn1_b,
                                 const float* __restrict__ bn1_m, const float* __restrict__ bn1_v,
                                 const float* __restrict__ conv2_w, const float* __restrict__ conv2_b,
                                 const float* __restrict__ bn2_g, const float* __restrict__ bn2_b,
                                 const float* __restrict__ bn2_m, const float* __restrict__ bn2_v,
                                 const float* __restrict__ out_w)
{
    int t = threadIdx.x;
    __shared__ uint32_t wb1[32];
    __shared__ float c1s[32], c0s[32];
    if (t < 32) {
        uint32_t wb = 0;
        #pragma unroll
        for (int k = 0; k < 9; k++) wb |= (conv1_w[t * 9 + k] > 0.0f) ? (1u << k) : 0u;
        wb1[t] = wb;
        float inv = __fdiv_rn(bn1_g[t], __fsqrt_rn(bn1_v[t] + 1e-5f));
        c1s[t] = inv;
        c0s[t] = conv1_b[t] * inv + bn1_b[t] - bn1_m[t] * inv;
    }
    __syncthreads();
    for (int idx = t; idx < 512; idx += 256) {
        uint32_t word = 0;
        #pragma unroll
        for (int oc = 0; oc < 32; oc++) {
            int pb = __popc((uint32_t)idx ^ wb1[oc]);
            float s = (float)(9 - 2 * pb);
            float val = fmaf(s, c1s[oc], c0s[oc]);
            if (val > 0.0f) word |= (1u << oc);
        }
        g_lut1[idx] = word;
    }
    for (int e = t; e < 576; e += 256) {
        int oc = e / 9, tap = e % 9;
        uint32_t w = 0;
        #pragma unroll
        for (int c = 0; c < 32; c++)
            w |= (conv2_w[oc * 288 + c * 9 + tap] > 0.0f) ? (1u << c) : 0u;
        g_wpos2[e] = w;
    }
    if (t < 64) {
        float inv = __fdiv_rn(bn2_g[t], __fsqrt_rn(bn2_v[t] + 1e-5f));
        g_c1_2[t] = inv;
        g_c0_2[t] = conv2_b[t] * inv + bn2_b[t] - bn2_m[t] * inv;
    }
    if (t < 160) {
        int k = t / 16, g = t % 16;
        uint32_t w = 0;
        #pragma unroll
        for (int b2 = 0; b2 < 32; b2++) {
            int n = g * 32 + b2;
            if (n < 500 && out_w[k * 500 + n] > 0.0f) w |= (1u << b2);
        }
        g_wposO[t] = w;
    }
}

// ---------------- prep (lin): coalesced read + smem transpose pack ---------
__global__ void prep_lin_kernel(const float* __restrict__ lin_w)
{
    __shared__ uint8_t sb[3840];
    int n = blockIdx.x;                 // 0..499
    const float* row = lin_w + n * 3840;
    for (int i = threadIdx.x; i < 3840; i += 256)
        sb[i] = row[i] > 0.0f ? 1 : 0;
    __syncthreads();
    for (int j = threadIdx.x; j < 128; j += 256) {
        uint32_t w = 0;
        if (j < 120) {
            int sp = j >> 1;
            int cb = (j & 1) * 32;
            #pragma unroll
            for (int b = 0; b < 32; b++)
                w |= (uint32_t)sb[(cb + b) * 60 + sp] << b;
        }
        g_wposL[n * 128 + j] = w;
    }
}

// ---------------- conv1: sign-pack x + 9-bit-patch LUT --------------------
__global__ void conv1_kernel(const float* __restrict__ x)
{
    __shared__ uint32_t rb[24][2];
    __shared__ uint32_t lut[512];
    int t = threadIdx.x;
    int b = blockIdx.x;
    int lane = t & 31, w = t >> 5;
    #pragma unroll
    for (int i = 0; i < 4; i++) lut[t + i * 128] = g_lut1[t + i * 128];
    const float* xb = x + b * 1296;
    for (int r = w; r < 24; r += 4) {
        const float* xr = xb + r * 54;
        uint32_t m0 = __ballot_sync(0xffffffffu, xr[lane] > 0.0f);
        float v2 = (lane < 22) ? xr[32 + lane] : -1.0f;
        uint32_t m1 = __ballot_sync(0xffffffffu, v2 > 0.0f);
        if (lane == 0) { rb[r][0] = m0; rb[r][1] = m1; }
    }
    __syncthreads();
    for (int p = t; p < A1W; p += 128) {
        int oy = p / 26, ox = p % 26;
        int sh = 2 * ox;
        uint32_t idx = 0;
        #pragma unroll
        for (int i = 0; i < 3; i++) {
            int r = 2 * oy + i;
            uint64_t row = (uint64_t)rb[r][0] | ((uint64_t)rb[r][1] << 32);
            idx |= (((uint32_t)(row >> sh)) & 7u) << (3 * i);
        }
        g_A1[b * A1W + p] = lut[idx];
    }
}

// ---------------- conv2: smem-staged popcount conv, warp = batch elem ------
__global__ void __launch_bounds__(256) conv2_kernel()
{
    __shared__ uint32_t sA[8][288];
    __shared__ uint32_t sO[120][8];
    int t = threadIdx.x, warp = t >> 5, lane = t & 31;
    int b0 = blockIdx.x * 8;

    for (int i = t; i < 8 * A1W; i += 256) {
        int e = i / A1W, p = i - e * A1W;
        sA[e][p] = g_A1[(b0 + e) * A1W + p];
    }
    uint32_t w0[9], w1[9];
    #pragma unroll
    for (int k = 0; k < 9; k++) {
        w0[k] = g_wpos2[lane * 9 + k];
        w1[k] = g_wpos2[(lane + 32) * 9 + k];
    }
    float c1a = g_c1_2[lane], c0a = g_c0_2[lane];
    float c1b = g_c1_2[lane + 32], c0b = g_c0_2[lane + 32];
    __syncthreads();

    const uint32_t* A = sA[warp];
    #pragma unroll 1
    for (int oy = 0; oy < 5; oy++) {
        #pragma unroll 2
        for (int ox = 0; ox < 12; ox++) {
            const uint32_t* base = A + oy * 52 + ox * 2;
            uint32_t a[9];
            #pragma unroll
            for (int i = 0; i < 3; i++)
                #pragma unroll
                for (int j = 0; j < 3; j++)
                    a[i * 3 + j] = base[i * 26 + j];
            int Asum = 0;
            #pragma unroll
            for (int k = 0; k < 9; k++) Asum += __popc(a[k]);
            int P0 = 0, P1 = 0;
            #pragma unroll
            for (int k = 0; k < 9; k++) {
                P0 += __popc(a[k] & w0[k]);
                P1 += __popc(a[k] & w1[k]);
            }
            float f0 = fmaf((float)(2 * P0 - Asum), c1a, c0a);
            float f1 = fmaf((float)(2 * P1 - Asum), c1b, c0b);
            uint32_t m0 = __ballot_sync(0xffffffffu, f0 > 0.0f);
            uint32_t m1 = __ballot_sync(0xffffffffu, f1 > 0.0f);
            int sp = oy * 12 + ox;
            if (lane == 0) sO[2 * sp][warp] = m0;
            if (lane == 1) sO[2 * sp + 1][warp] = m1;
        }
    }
    __syncthreads();

    for (int i = t; i < 960; i += 256) {
        int j = i >> 3, u = i & 7;
        g_tT[j * NB + b0 + u] = sO[j][u];
    }
}

// ---------------- lin: popcount GEMM, 2-m register blocking ----------------
// block = 128 thr = 4 warps; thread handles rows (mA, mA+32) x 32 n.
// block covers 256 m x 32 n; grid = 32 m-tiles x 16 n-groups = 512 blocks.
__global__ void __launch_bounds__(128) lin_kernel(const float* __restrict__ lin_b)
{
    __shared__ uint4 sw[32][30];        // 32 n rows x 120 words = 15 KB
    __shared__ float sbias[32];
    int t = threadIdx.x;
    int ng = blockIdx.x & 15;
    int mt = blockIdx.x >> 4;           // 0..31
    int lane = t & 31, warp = t >> 5;

    const uint4* wsrc = reinterpret_cast<const uint4*>(g_wposL) + (ng * 32) * 32;
    for (int i = t; i < 960; i += 128) {
        int n = i / 30, q = i - n * 30;
        sw[n][q] = wsrc[n * 32 + q];
    }
    if (t < 32) {
        int gn = ng * 32 + t;
        sbias[t] = (gn < 500) ? lin_b[gn] : 0.0f;
    }
    __syncthreads();

    int mA = mt * 256 + warp * 64 + lane;
    int mB = mA + 32;

    uint32_t acc[32];                   // low 16 = mA popcount, high 16 = mB
    #pragma unroll
    for (int n = 0; n < 32; n++) acc[n] = 0;
    int SA = 0, SB = 0;

    #pragma unroll 1
    for (int kc = 0; kc < 10; kc++) {   // 10 chunks x 12 words
        uint32_t twA[12], twB[12];
        #pragma unroll
        for (int u = 0; u < 12; u++) {
            twA[u] = g_tT[(kc * 12 + u) * NB + mA];
            twB[u] = g_tT[(kc * 12 + u) * NB + mB];
        }
        #pragma unroll
        for (int u = 0; u < 12; u++) { SA += __popc(twA[u]); SB += __popc(twB[u]); }
        #pragma unroll 8
        for (int n = 0; n < 32; n++) {
            int pA = 0, pB = 0;
            #pragma unroll
            for (int q = 0; q < 3; q++) {
                uint4 wv = sw[n][kc * 3 + q];
                pA += __popc(twA[q * 4 + 0] & wv.x) + __popc(twA[q * 4 + 1] & wv.y)
                    + __popc(twA[q * 4 + 2] & wv.z) + __popc(twA[q * 4 + 3] & wv.w);
                pB += __popc(twB[q * 4 + 0] & wv.x) + __popc(twB[q * 4 + 1] & wv.y)
                    + __popc(twB[q * 4 + 2] & wv.z) + __popc(twB[q * 4 + 3] & wv.w);
            }
            acc[n] += (uint32_t)pA + ((uint32_t)pB << 16);
        }
    }

    uint32_t bitsA = 0, bitsB = 0;
    #pragma unroll
    for (int n = 0; n < 32; n++) {
        int gn = ng * 32 + n;
        if (gn < 500) {
            float b = sbias[n];
            float preA = (float)(2 * (int)(acc[n] & 0xffffu) - SA) + b;
            float preB = (float)(2 * (int)(acc[n] >> 16) - SB) + b;
            if (preA > 0.0f) bitsA |= (1u << n);
            if (preB > 0.0f) bitsB |= (1u << n);
        }
    }
    g_B2[mA * 16 + ng] = bitsA;
    g_B2[mB * 16 + ng] = bitsB;
}

// ---------------- out: 500->10 popcount matmul -----------------------------
__global__ void out_kernel(const float* __restrict__ out_b, float* __restrict__ y)
{
    __shared__ uint32_t wO[160];
    __shared__ float ob[10];
    int t = threadIdx.x;
    if (t < 160) wO[t] = g_wposO[t];
    if (t < 10)  ob[t] = out_b[t];
    __syncthreads();
    int m = blockIdx.x * 256 + t;
    uint32_t tw[16];
    const uint4* p = reinterpret_cast<const uint4*>(g_B2 + m * 16);
    #pragma unroll
    for (int q = 0; q < 4; q++) {
        uint4 v = p[q];
        tw[q * 4 + 0] = v.x; tw[q * 4 + 1] = v.y;
        tw[q * 4 + 2] = v.z; tw[q * 4 + 3] = v.w;
    }
    int S2 = 0;
    #pragma unroll
    for (int g = 0; g < 16; g++) S2 += __popc(tw[g]);
    #pragma unroll
    for (int k = 0; k < 10; k++) {
        int acc = 0;
        #pragma unroll
        for (int g = 0; g < 16; g++) acc += __popc(tw[g] & wO[k * 16 + g]);
        y[m * 10 + k] = (float)(2 * acc - S2) + ob[k];
    }
}

// ---------------- launch ----------------------------------------------------
extern "C" void kernel_launch(void* const* d_in, const int* in_sizes, int n_in,
                              void* d_out, int out_size)
{
    const float* x       = (const float*)d_in[0];
    const float* conv1_w = (const float*)d_in[1];
    const float* conv1_b = (const float*)d_in[2];
    const float* bn1_g   = (const float*)d_in[3];
    const float* bn1_b   = (const float*)d_in[4];
    const float* bn1_m   = (const float*)d_in[5];
    const float* bn1_v   = (const float*)d_in[6];
    const float* conv2_w = (const float*)d_in[7];
    const float* conv2_b = (const float*)d_in[8];
    const float* bn2_g   = (const float*)d_in[9];
    const float* bn2_b   = (const float*)d_in[10];
    const float* bn2_m   = (const float*)d_in[11];
    const float* bn2_v   = (const float*)d_in[12];
    const float* lin_w   = (const float*)d_in[13];
    const float* lin_b   = (const float*)d_in[14];
    const float* out_w   = (const float*)d_in[15];
    const float* out_b   = (const float*)d_in[16];

    prep_misc_kernel<<<1, 256>>>(conv1_w, conv1_b, bn1_g, bn1_b, bn1_m, bn1_v,
                                 conv2_w, conv2_b, bn2_g, bn2_b, bn2_m, bn2_v,
                                 out_w);
    prep_lin_kernel<<<500, 256>>>(lin_w);
    conv1_kernel<<<NB, 128>>>(x);
    conv2_kernel<<<NB / 8, 256>>>();
    lin_kernel<<<512, 128>>>(lin_b);
    out_kernel<<<NB / 256, 256>>>(out_b, (float*)d_out);
}

// round 5
// speedup vs baseline: 1.1233x; 1.1233x over previous
#include <cuda_runtime.h>
#include <cstdint>

#define NB 8192           // batch
#define A1W 286           // 11*26 conv1 output pixels per batch elem

// ---------------- scratch (device globals; no allocation allowed) ----------
__device__ uint32_t g_lut1[512];                       // conv1+bn1+relu+binarize LUT
__device__ uint32_t g_wpos2[64 * 9];                   // conv2 weight sign bits [oc][tap]
__device__ float    g_c1_2[64], g_c0_2[64];            // conv2 bn affine
__device__ __align__(16) uint32_t g_wposL[512 * 128];  // lin weight bits [n(pad512)][j(pad128)]
__device__ uint32_t g_wposO[10 * 16];                  // out weight bits [k][g]
__device__ uint32_t g_A1[NB * A1W];                    // conv1 output, 32ch packed per pixel
__device__ uint32_t g_tT[120 * NB];                    // conv2 output bits, transposed [j][m]
__device__ __align__(16) uint32_t g_B2[NB * 16];       // lin output bits [m][16 words]

// ---------------- prep (misc): LUTs, conv2 weights, out weights ------------
__global__ void prep_misc_kernel(const float* __restrict__ conv1_w, const float* __restrict__ conv1_b,
                                 const float* __restrict__ bn1_g, const float* __restrict__ bn1_b,
                                 const float* __restrict__ bn1_m, const float* __restrict__ bn1_v,
                                 const float* __restrict__ conv2_w, const float* __restrict__ conv2_b,
                                 const float* __restrict__ bn2_g, const float* __restrict__ bn2_b,
                                 const float* __restrict__ bn2_m, const float* __restrict__ bn2_v,
                                 const float* __restrict__ out_w)
{
    int t = threadIdx.x;
    __shared__ uint32_t wb1[32];
    __shared__ float c1s[32], c0s[32];
    if (t < 32) {
        uint32_t wb = 0;
        #pragma unroll
        for (int k = 0; k < 9; k++) wb |= (conv1_w[t * 9 + k] > 0.0f) ? (1u << k) : 0u;
        wb1[t] = wb;
        float inv = __fdiv_rn(bn1_g[t], __fsqrt_rn(bn1_v[t] + 1e-5f));
        c1s[t] = inv;
        c0s[t] = conv1_b[t] * inv + bn1_b[t] - bn1_m[t] * inv;
    }
    __syncthreads();
    for (int idx = t; idx < 512; idx += 256) {
        uint32_t word = 0;
        #pragma unroll
        for (int oc = 0; oc < 32; oc++) {
            int pb = __popc((uint32_t)idx ^ wb1[oc]);
            float s = (float)(9 - 2 * pb);
            float val = fmaf(s, c1s[oc], c0s[oc]);
            if (val > 0.0f) word |= (1u << oc);
        }
        g_lut1[idx] = word;
    }
    for (int e = t; e < 576; e += 256) {
        int oc = e / 9, tap = e % 9;
        uint32_t w = 0;
        #pragma unroll
        for (int c = 0; c < 32; c++)
            w |= (conv2_w[oc * 288 + c * 9 + tap] > 0.0f) ? (1u << c) : 0u;
        g_wpos2[e] = w;
    }
    if (t < 64) {
        float inv = __fdiv_rn(bn2_g[t], __fsqrt_rn(bn2_v[t] + 1e-5f));
        g_c1_2[t] = inv;
        g_c0_2[t] = conv2_b[t] * inv + bn2_b[t] - bn2_m[t] * inv;
    }
    if (t < 160) {
        int k = t / 16, g = t % 16;
        uint32_t w = 0;
        #pragma unroll
        for (int b2 = 0; b2 < 32; b2++) {
            int n = g * 32 + b2;
            if (n < 500 && out_w[k * 500 + n] > 0.0f) w |= (1u << b2);
        }
        g_wposO[t] = w;
    }
}

// ---------------- prep (lin): coalesced read + smem transpose pack ---------
__global__ void prep_lin_kernel(const float* __restrict__ lin_w)
{
    __shared__ uint8_t sb[3840];
    int n = blockIdx.x;                 // 0..499
    const float* row = lin_w + n * 3840;
    for (int i = threadIdx.x; i < 3840; i += 256)
        sb[i] = row[i] > 0.0f ? 1 : 0;
    __syncthreads();
    for (int j = threadIdx.x; j < 128; j += 256) {
        uint32_t w = 0;
        if (j < 120) {
            int sp = j >> 1;
            int cb = (j & 1) * 32;
            #pragma unroll
            for (int b = 0; b < 32; b++)
                w |= (uint32_t)sb[(cb + b) * 60 + sp] << b;
        }
        g_wposL[n * 128 + j] = w;
    }
}

// ---------------- conv1: sign-pack x + 9-bit-patch LUT --------------------
__global__ void conv1_kernel(const float* __restrict__ x)
{
    __shared__ uint32_t rb[24][2];
    __shared__ uint32_t lut[512];
    int t = threadIdx.x;
    int b = blockIdx.x;
    int lane = t & 31, w = t >> 5;
    #pragma unroll
    for (int i = 0; i < 4; i++) lut[t + i * 128] = g_lut1[t + i * 128];
    const float* xb = x + b * 1296;
    for (int r = w; r < 24; r += 4) {
        const float* xr = xb + r * 54;
        uint32_t m0 = __ballot_sync(0xffffffffu, xr[lane] > 0.0f);
        float v2 = (lane < 22) ? xr[32 + lane] : -1.0f;
        uint32_t m1 = __ballot_sync(0xffffffffu, v2 > 0.0f);
        if (lane == 0) { rb[r][0] = m0; rb[r][1] = m1; }
    }
    __syncthreads();
    for (int p = t; p < A1W; p += 128) {
        int oy = p / 26, ox = p % 26;
        int sh = 2 * ox;
        uint32_t idx = 0;
        #pragma unroll
        for (int i = 0; i < 3; i++) {
            int r = 2 * oy + i;
            uint64_t row = (uint64_t)rb[r][0] | ((uint64_t)rb[r][1] << 32);
            idx |= (((uint32_t)(row >> sh)) & 7u) << (3 * i);
        }
        g_A1[b * A1W + p] = lut[idx];
    }
}

// ---------------- conv2: window-batched popcount conv, warp = batch elem ---
// block = 128 thr = 4 warps = 4 elems; grid = NB/4 = 2048
__global__ void __launch_bounds__(128) conv2_kernel()
{
    __shared__ uint32_t sA[4][288];     // 4 batch elems x 286 words
    __shared__ uint32_t sO[120][4];     // output bits staging [j][elem]
    int t = threadIdx.x, warp = t >> 5, lane = t & 31;
    int b0 = blockIdx.x * 4;

    for (int i = t; i < 4 * A1W; i += 128) {
        int e = i / A1W, p = i - e * A1W;
        sA[e][p] = g_A1[(b0 + e) * A1W + p];
    }
    uint32_t w0[9], w1[9];
    #pragma unroll
    for (int k = 0; k < 9; k++) {
        w0[k] = g_wpos2[lane * 9 + k];
        w1[k] = g_wpos2[(lane + 32) * 9 + k];
    }
    float c1a = g_c1_2[lane], c0a = g_c0_2[lane];
    float c1b = g_c1_2[lane + 32], c0b = g_c0_2[lane + 32];
    __syncthreads();

    const uint32_t* A = sA[warp];
    #pragma unroll 1
    for (int oy = 0; oy < 5; oy++) {
        const uint32_t* R = A + oy * 52;          // rows 2oy,2oy+1,2oy+2 @ +0,+26,+52
        #pragma unroll
        for (int g = 0; g < 2; g++) {
            // window: 13 cols (g*12 .. g*12+12) x 3 rows, fully static
            uint32_t v[3][13];
            #pragma unroll
            for (int i = 0; i < 3; i++)
                #pragma unroll
                for (int c = 0; c < 13; c++)
                    v[i][c] = R[i * 26 + g * 12 + c];
            int cs[13];
            #pragma unroll
            for (int c = 0; c < 13; c++)
                cs[c] = __popc(v[0][c]) + __popc(v[1][c]) + __popc(v[2][c]);
            #pragma unroll
            for (int px = 0; px < 6; px++) {
                int c0 = px * 2;
                int Asum = cs[c0] + cs[c0 + 1] + cs[c0 + 2];
                int P0 = 0, P1 = 0;
                #pragma unroll
                for (int i = 0; i < 3; i++)
                    #pragma unroll
                    for (int j = 0; j < 3; j++) {
                        uint32_t a = v[i][c0 + j];
                        P0 += __popc(a & w0[i * 3 + j]);
                        P1 += __popc(a & w1[i * 3 + j]);
                    }
                float f0 = fmaf((float)(2 * P0 - Asum), c1a, c0a);
                float f1 = fmaf((float)(2 * P1 - Asum), c1b, c0b);
                uint32_t m0 = __ballot_sync(0xffffffffu, f0 > 0.0f);
                uint32_t m1 = __ballot_sync(0xffffffffu, f1 > 0.0f);
                int sp = oy * 12 + g * 6 + px;
                if (lane == 0) sO[2 * sp][warp] = m0;
                if (lane == 1) sO[2 * sp + 1][warp] = m1;
            }
        }
    }
    __syncthreads();

    for (int i = t; i < 480; i += 128) {
        int j = i >> 2, u = i & 3;
        g_tT[j * NB + b0 + u] = sO[j][u];
    }
}

// ---------------- lin: popcount GEMM, warp = 32m x 32n, smem weights -------
// (R3 version — proven fastest so far)
__global__ void __launch_bounds__(128) lin_kernel(const float* __restrict__ lin_b)
{
    __shared__ uint4 sw[32][30];        // 32 n rows x 120 words = 15 KB
    int t = threadIdx.x;
    int ng = blockIdx.x & 15;
    int mg = (blockIdx.x >> 4) * 4 + (t >> 5);
    int lane = t & 31;

    const uint4* wsrc = reinterpret_cast<const uint4*>(g_wposL) + (ng * 32) * 32;
    for (int i = t; i < 960; i += 128) {
        int n = i / 30, q = i - n * 30;
        sw[n][q] = wsrc[n * 32 + q];
    }
    __syncthreads();

    int m = mg * 32 + lane;
    int acc[32];
    #pragma unroll
    for (int n = 0; n < 32; n++) acc[n] = 0;
    int S = 0;

    #pragma unroll 1
    for (int kc = 0; kc < 5; kc++) {
        uint32_t tw[24];
        #pragma unroll
        for (int u = 0; u < 24; u++) tw[u] = g_tT[(kc * 24 + u) * NB + m];
        #pragma unroll
        for (int u = 0; u < 24; u++) S += __popc(tw[u]);
        #pragma unroll
        for (int n = 0; n < 32; n++) {
            int p = 0;
            #pragma unroll
            for (int q = 0; q < 6; q++) {
                uint4 wv = sw[n][kc * 6 + q];
                p += __popc(tw[q * 4 + 0] & wv.x);
                p += __popc(tw[q * 4 + 1] & wv.y);
                p += __popc(tw[q * 4 + 2] & wv.z);
                p += __popc(tw[q * 4 + 3] & wv.w);
            }
            acc[n] += p;
        }
    }

    uint32_t bits = 0;
    #pragma unroll
    for (int n = 0; n < 32; n++) {
        int gn = ng * 32 + n;
        if (gn < 500) {
            float pre = (float)(2 * acc[n] - S) + lin_b[gn];
            if (pre > 0.0f) bits |= (1u << n);
        }
    }
    g_B2[m * 16 + ng] = bits;
}

// ---------------- out: 500->10 popcount matmul -----------------------------
__global__ void out_kernel(const float* __restrict__ out_b, float* __restrict__ y)
{
    __shared__ uint32_t wO[160];
    __shared__ float ob[10];
    int t = threadIdx.x;
    if (t < 160) wO[t] = g_wposO[t];
    if (t < 10)  ob[t] = out_b[t];
    __syncthreads();
    int m = blockIdx.x * 256 + t;
    uint32_t tw[16];
    const uint4* p = reinterpret_cast<const uint4*>(g_B2 + m * 16);
    #pragma unroll
    for (int q = 0; q < 4; q++) {
        uint4 v = p[q];
        tw[q * 4 + 0] = v.x; tw[q * 4 + 1] = v.y;
        tw[q * 4 + 2] = v.z; tw[q * 4 + 3] = v.w;
    }
    int S2 = 0;
    #pragma unroll
    for (int g = 0; g < 16; g++) S2 += __popc(tw[g]);
    #pragma unroll
    for (int k = 0; k < 10; k++) {
        int acc = 0;
        #pragma unroll
        for (int g = 0; g < 16; g++) acc += __popc(tw[g] & wO[k * 16 + g]);
        y[m * 10 + k] = (float)(2 * acc - S2) + ob[k];
    }
}

// ---------------- launch ----------------------------------------------------
extern "C" void kernel_launch(void* const* d_in, const int* in_sizes, int n_in,
                              void* d_out, int out_size)
{
    const float* x       = (const float*)d_in[0];
    const float* conv1_w = (const float*)d_in[1];
    const float* conv1_b = (const float*)d_in[2];
    const float* bn1_g   = (const float*)d_in[3];
    const float* bn1_b   = (const float*)d_in[4];
    const float* bn1_m   = (const float*)d_in[5];
    const float* bn1_v   = (const float*)d_in[6];
    const float* conv2_w = (const float*)d_in[7];
    const float* conv2_b = (const float*)d_in[8];
    const float* bn2_g   = (const float*)d_in[9];
    const float* bn2_b   = (const float*)d_in[10];
    const float* bn2_m   = (const float*)d_in[11];
    const float* bn2_v   = (const float*)d_in[12];
    const float* lin_w   = (const float*)d_in[13];
    const float* lin_b   = (const float*)d_in[14];
    const float* out_w   = (const float*)d_in[15];
    const float* out_b   = (const float*)d_in[16];

    prep_misc_kernel<<<1, 256>>>(conv1_w, conv1_b, bn1_g, bn1_b, bn1_m, bn1_v,
                                 conv2_w, conv2_b, bn2_g, bn2_b, bn2_m, bn2_v,
                                 out_w);
    prep_lin_kernel<<<500, 256>>>(lin_w);
    conv1_kernel<<<NB, 128>>>(x);
    conv2_kernel<<<NB / 4, 128>>>();
    lin_kernel<<<1024, 128>>>(lin_b);
    out_kernel<<<NB / 256, 256>>>(out_b, (float*)d_out);
}